// round 1
// baseline (speedup 1.0000x reference)
#include <cuda_runtime.h>

#define B_  32
#define NJ  2048
#define IL  32
#define CC  32
#define LL  32
#define KK  1024  // CC*LL

// Scratch (allocation-free rule: __device__ globals)
__device__ float g_u[(size_t)B_ * NJ * KK];   // 256 MiB, layout [b][j][k]
__device__ float g_b[(size_t)B_ * NJ * CC];   // routing logits
__device__ float g_s[B_ * KK];                // s accumulator
__device__ float g_v[B_ * KK];                // current v

// ---------------------------------------------------------------------------
// Kernel 1: u[b,j,k] = sum_i x[b,j,i] * W[j,i,k].  One block per j.
// ---------------------------------------------------------------------------
__global__ void gemm_u(const float* __restrict__ x, const float* __restrict__ W) {
    int j = blockIdx.x;
    int t = threadIdx.x;
    __shared__ float xs[B_ * IL];
    {
        int b  = t >> 3;
        int i0 = (t & 7) << 2;
        *(float4*)(xs + b * IL + i0) =
            *(const float4*)(x + ((size_t)b * NJ + j) * IL + i0);
    }
    __syncthreads();
    const float* Wj = W + (size_t)j * IL * KK;
    #pragma unroll 1
    for (int kk = 0; kk < 4; ++kk) {
        int k = t + (kk << 8);
        float acc[B_];
        #pragma unroll
        for (int b = 0; b < B_; ++b) acc[b] = 0.f;
        #pragma unroll 4
        for (int i = 0; i < IL; ++i) {
            float w = __ldg(Wj + i * KK + k);
            #pragma unroll
            for (int b = 0; b < B_; ++b)
                acc[b] = fmaf(xs[b * IL + i], w, acc[b]);
        }
        float* up = g_u + (size_t)j * KK + k;
        #pragma unroll
        for (int b = 0; b < B_; ++b)
            up[(size_t)b * NJ * KK] = acc[b];
    }
}

// ---------------------------------------------------------------------------
// Kernel 2: iteration 0 (uniform coupling 1/32): s0 = sum_j u / 32 + bias,
// v0 = squash(s0).  One block per (b,c).
// ---------------------------------------------------------------------------
__global__ void s0v0(const float* __restrict__ biases) {
    int c = blockIdx.x, b = blockIdx.y;
    int t = threadIdx.x;
    const float4* up = (const float4*)(g_u + (size_t)b * NJ * KK + c * LL);
    int l4 = t & 7, jg = t >> 3;
    float4 a = make_float4(0.f, 0.f, 0.f, 0.f);
    for (int j = jg; j < NJ; j += 32) {
        float4 r = up[j * (KK / 4) + l4];
        a.x += r.x; a.y += r.y; a.z += r.z; a.w += r.w;
    }
    __shared__ float4 sm[256];
    sm[t] = a;
    __syncthreads();
    #pragma unroll
    for (int off = 128; off >= 8; off >>= 1) {
        if (t < off) {
            float4 o = sm[t + off];
            float4 s = sm[t];
            s.x += o.x; s.y += o.y; s.z += o.z; s.w += o.w;
            sm[t] = s;
        }
        __syncthreads();
    }
    if (t < 8) {
        float4 s = sm[t];
        const float inv = 1.0f / 32.0f;
        float4 bi = ((const float4*)biases)[c * 8 + t];
        s.x = s.x * inv + bi.x;
        s.y = s.y * inv + bi.y;
        s.z = s.z * inv + bi.z;
        s.w = s.w * inv + bi.w;
        float p = s.x * s.x + s.y * s.y + s.z * s.z + s.w * s.w;
        p += __shfl_xor_sync(0xffu, p, 4);
        p += __shfl_xor_sync(0xffu, p, 2);
        p += __shfl_xor_sync(0xffu, p, 1);
        float n = sqrtf(p);
        float coef = p / ((1.0f + p) * (n + 1e-7f));
        float4 v = make_float4(coef * s.x, coef * s.y, coef * s.z, coef * s.w);
        ((float4*)g_v)[(b * CC + c) * 8 + t] = v;
    }
}

__global__ void zero_s() { g_s[blockIdx.x * 1024 + threadIdx.x] = 0.f; }

// ---------------------------------------------------------------------------
// Kernel 3: fused routing pass.  For each (b,j):
//   bnew[c] = (read_b ? b_old[c] : 0) + dot_l(u[b,j,c,:], v[b,c,:])
//   coup    = softmax_c(bnew)
//   s[b,c,l] += coup[c] * u[b,j,c,l]
// Warp owns 16 j rows; lane holds k = 128q + 4*lane (+0..3) per q.
//   => c(q) = 4q + (lane>>3), l = 4*(lane&7)+comp
// ---------------------------------------------------------------------------
__global__ void route_pass(int read_b, int write_b) {
    int b = blockIdx.y;
    int t = threadIdx.x, w = t >> 5, lane = t & 31;
    int g = lane >> 3, sub = lane & 7;
    __shared__ float4 vs4[256];
    __shared__ float4 sred[8][256];
    vs4[t] = ((const float4*)g_v)[b * 256 + t];
    __syncthreads();

    float4 acc[8];
    #pragma unroll
    for (int q = 0; q < 8; ++q) acc[q] = make_float4(0.f, 0.f, 0.f, 0.f);

    int j0 = blockIdx.x * 128 + w * 16;
    for (int jj = 0; jj < 16; ++jj) {
        int j = j0 + jj;
        const float4* up = (const float4*)(g_u + ((size_t)b * NJ + j) * KK);
        float4 r[8];
        #pragma unroll
        for (int q = 0; q < 8; ++q) r[q] = up[q * 32 + lane];

        float dots[8];
        #pragma unroll
        for (int q = 0; q < 8; ++q) {
            float4 vv = vs4[q * 32 + lane];
            float d = r[q].x * vv.x + r[q].y * vv.y + r[q].z * vv.z + r[q].w * vv.w;
            d += __shfl_xor_sync(0xffffffffu, d, 1);
            d += __shfl_xor_sync(0xffffffffu, d, 2);
            d += __shfl_xor_sync(0xffffffffu, d, 4);
            dots[q] = d;   // full dot for c = 4q + g, replicated over 8 lanes
        }

        size_t bbase = ((size_t)b * NJ + j) * CC;
        if (read_b) {
            float bl = g_b[bbase + lane];   // lane holds b_old for c = lane
            #pragma unroll
            for (int q = 0; q < 8; ++q)
                dots[q] += __shfl_sync(0xffffffffu, bl, 4 * q + g);
        }
        if (write_b) {
            float wv = dots[0];
            #pragma unroll
            for (int q = 1; q < 8; ++q)
                if (sub == q) wv = dots[q];
            g_b[bbase + 4 * sub + g] = wv;  // bijective lane -> c map
        }

        // softmax over all 32 c
        float m = dots[0];
        #pragma unroll
        for (int q = 1; q < 8; ++q) m = fmaxf(m, dots[q]);
        m = fmaxf(m, __shfl_xor_sync(0xffffffffu, m, 8));
        m = fmaxf(m, __shfl_xor_sync(0xffffffffu, m, 16));
        float e[8], se = 0.f;
        #pragma unroll
        for (int q = 0; q < 8; ++q) { e[q] = __expf(dots[q] - m); se += e[q]; }
        se += __shfl_xor_sync(0xffffffffu, se, 8);
        se += __shfl_xor_sync(0xffffffffu, se, 16);
        float inv = 1.0f / se;

        #pragma unroll
        for (int q = 0; q < 8; ++q) {
            float cp = e[q] * inv;
            acc[q].x = fmaf(cp, r[q].x, acc[q].x);
            acc[q].y = fmaf(cp, r[q].y, acc[q].y);
            acc[q].z = fmaf(cp, r[q].z, acc[q].z);
            acc[q].w = fmaf(cp, r[q].w, acc[q].w);
        }
    }

    #pragma unroll
    for (int q = 0; q < 8; ++q) sred[w][q * 32 + lane] = acc[q];
    __syncthreads();

    float4 ssum = sred[0][t];
    #pragma unroll
    for (int ww = 1; ww < 8; ++ww) {
        float4 o = sred[ww][t];
        ssum.x += o.x; ssum.y += o.y; ssum.z += o.z; ssum.w += o.w;
    }
    float* sp = g_s + b * KK + t * 4;
    atomicAdd(sp + 0, ssum.x);
    atomicAdd(sp + 1, ssum.y);
    atomicAdd(sp + 2, ssum.z);
    atomicAdd(sp + 3, ssum.w);
}

// ---------------------------------------------------------------------------
// Kernel 4: v = squash(s + bias).  One warp per (b,c).
// ---------------------------------------------------------------------------
__global__ void finalize(const float* __restrict__ biases,
                         float* __restrict__ out, int write_out) {
    int t = threadIdx.x, w = t >> 5, lane = t & 31;
    int bc = blockIdx.x * 8 + w;
    int c = bc & 31;
    float s = g_s[bc * 32 + lane] + biases[c * 32 + lane];
    float p = s * s;
    #pragma unroll
    for (int off = 16; off; off >>= 1)
        p += __shfl_xor_sync(0xffffffffu, p, off);
    float n = sqrtf(p);
    float coef = p / ((1.0f + p) * (n + 1e-7f));
    float v = coef * s;
    if (write_out) out[bc * 32 + lane] = v;
    else           g_v[bc * 32 + lane] = v;
}

// ---------------------------------------------------------------------------
extern "C" void kernel_launch(void* const* d_in, const int* in_sizes, int n_in,
                              void* d_out, int out_size) {
    const float* x      = (const float*)d_in[0];  // [B,H,W,iC,iL] == [B,NJ,IL]
    const float* W      = (const float*)d_in[1];  // [NJ, IL, KK]
    const float* biases = (const float*)d_in[2];  // [CC, LL]
    float* out = (float*)d_out;                   // [B, CC, LL]

    gemm_u<<<NJ, 256>>>(x, W);
    s0v0<<<dim3(CC, B_), 256>>>(biases);          // r=0: s0, v0

    zero_s<<<32, 1024>>>();
    route_pass<<<dim3(16, B_), 256>>>(0, 1);      // b1 = dot(u,v0); c1; s1
    finalize<<<128, 256>>>(biases, out, 0);       // v1

    zero_s<<<32, 1024>>>();
    route_pass<<<dim3(16, B_), 256>>>(1, 0);      // b2 = b1 + dot(u,v1); c2; s2
    finalize<<<128, 256>>>(biases, out, 1);       // v2 -> output
}